// round 8
// baseline (speedup 1.0000x reference)
#include <cuda_runtime.h>
#include <cstdint>

// Problem constants
static constexpr int B = 2, N = 4, D = 48, H = 28, W = 60, C = 64;
static constexpr int DOWNSAMPLE = 8;
static constexpr int NX = 192, NY = 192, NZ = 1;
static constexpr float F_BEV = 4.0f;           // 1/SCALE
static constexpr float CX_BEV = 96.0f;         // NX/2 + OFFSETX
static constexpr float CY_BEV = 96.0f;         // NY/2
static constexpr float DMIN = 2.0f, DSTEP = 1.0f;

static constexpr int NCOL  = B * N * D * W;    // 23040 columns (b,n,d,w)
static constexpr int PLANE = NY * NX;          // 36864
static constexpr int OUT_ELEMS = B * NZ * C * PLANE;  // 4,718,592 floats
static constexpr int OUT_F4   = OUT_ELEMS / 4;        // 1,179,648 float4

// ---------------------------------------------------------------------------
// Kernel 0: zero d_out (output is the accumulator). Grid-stride float4 loop.
// ---------------------------------------------------------------------------
__global__ void zero_out(float* __restrict__ out) {
    float4* o4 = reinterpret_cast<float4*>(out);
    const float4 z = make_float4(0.f, 0.f, 0.f, 0.f);
    for (int i = blockIdx.x * blockDim.x + threadIdx.x; i < OUT_F4;
         i += gridDim.x * blockDim.x) {
        o4[i] = z;
    }
}

// ---------------------------------------------------------------------------
// Kernel 1: scatter directly into out (B, C, NY, NX).
// Thread = (column cid, channel-quad q). Warp = 2 columns x 16 quads.
// Phase 1: lane evaluates voxel(own col, h=q) and voxel(own col, h=q+16);
//          two ballots give per-column 28-bit kept masks -> warp-uniform
//          [hmin, hmax] kept interval.
// Phase 2: loop over [hmin, hmax] with UNCONDITIONAL float4 loads (no control
//          dependency -> ptxas batches them, MLP ~4-8); voxel via shuffle;
//          run-length accumulate; flush = 4 scalar red.add.f32.
// ---------------------------------------------------------------------------
__global__ __launch_bounds__(256) void scatter_kernel(
        const float* __restrict__ x,
        const float* __restrict__ intr,
        const float* __restrict__ pose,
        float* __restrict__ out) {
    __shared__ float s_geom[B * N * 12];

    if (threadIdx.x < B * N) {
        int i = threadIdx.x;
        const float* K = intr + i * 9;
        float a = K[0], b = K[1], c = K[2];
        float d = K[3], e = K[4], f = K[5];
        float g = K[6], h = K[7], ii = K[8];
        float A  = e * ii - f * h;
        float Bc = f * g - d * ii;
        float Cc = d * h - e * g;
        float inv_det = 1.0f / (a * A + b * Bc + c * Cc);
        float inv[9];
        inv[0] = A * inv_det;  inv[1] = (c * h - b * ii) * inv_det; inv[2] = (b * f - c * e) * inv_det;
        inv[3] = Bc * inv_det; inv[4] = (a * ii - c * g) * inv_det; inv[5] = (c * d - a * f) * inv_det;
        inv[6] = Cc * inv_det; inv[7] = (b * g - a * h) * inv_det;  inv[8] = (a * e - b * d) * inv_det;
        const float* P = pose + i * 16;
        for (int r = 0; r < 3; r++) {
            for (int cc = 0; cc < 3; cc++) {
                float s = 0.f;
                for (int k = 0; k < 3; k++) s += P[r * 4 + k] * inv[k * 3 + cc];
                s_geom[i * 12 + r * 3 + cc] = s;
            }
            s_geom[i * 12 + 9 + r] = P[r * 4 + 3];
        }
    }
    __syncthreads();

    const int gtid = blockIdx.x * 256 + threadIdx.x;   // 0 .. NCOL*16-1 (exact)
    const int lane = threadIdx.x & 31;
    const int q    = gtid & 15;
    const int cid  = gtid >> 4;

    // decode column (b,n,d,w):  cid = ((b*N+n)*D + d)*W + w
    const int w   = cid % W;
    const int bnd = cid / W;              // (b*N+n)*D + d
    const int dd  = bnd % D;
    const int bn  = bnd / D;              // b*N + n
    const int b   = bn >> 2;              // /N

    const float* cm = s_geom + bn * 12;
    const float cm0 = cm[0], cm1 = cm[1], cm2 = cm[2], cm9  = cm[9];
    const float cm3 = cm[3], cm4 = cm[4], cm5 = cm[5], cm10 = cm[10];
    const float cm6 = cm[6], cm7 = cm[7], cm8 = cm[8], cm11 = cm[11];

    const float STEPX = (float)(W * DOWNSAMPLE - 1) / (float)(W - 1);
    const float STEPY = (float)(H * DOWNSAMPLE - 1) / (float)(H - 1);
    const float dep = DMIN + (float)dd * DSTEP;
    const float px  = ((float)w * STEPX) * dep;
    const float pz  = dep;

    // --- Phase 1: this lane evaluates geometry for h = q and h = q+16 ---
    // identical fmaf chains to the verified kernels (bin-boundary stability)
    auto voxel_at = [&](int h) -> int {
        float v  = (float)h * STEPY;
        float py = v * dep;
        float gxf = fmaf(cm0, px, fmaf(cm1, py, fmaf(cm2, pz, cm9)));
        float gyf = fmaf(cm3, px, fmaf(cm4, py, fmaf(cm5, pz, cm10)));
        float gzf = fmaf(cm6, px, fmaf(cm7, py, fmaf(cm8, pz, cm11)));
        int gx = (int)(gxf * F_BEV + CX_BEV);     // trunc == astype(int32)
        int gy = (int)(gyf * F_BEV + CY_BEV);
        int gz = (int)((gzf + 10.0f) / 20.0f);
        bool kept = (gx >= 0) & (gx < NX) & (gy >= 0) & (gy < NY) & (gz >= 0) & (gz < NZ);
        return kept ? (gz * NY + gy) * NX + gx : -1;   // NZ=1 -> gz*NY*NX folds in
    };
    int v1 = voxel_at(q);
    int v2 = (q < 12) ? voxel_at(q + 16) : -1;

    // --- kept masks per column via ballots ---
    unsigned ballot1 = __ballot_sync(0xffffffffu, v1 >= 0);  // h 0..15, colA=bits0-15, colB=bits16-31
    unsigned ballot2 = __ballot_sync(0xffffffffu, v2 >= 0);  // h 16..27
    unsigned cmask = (ballot1 & 0xffffu) | (ballot1 >> 16)
                   | (((ballot2 & 0x0fffu) | ((ballot2 >> 16) & 0x0fffu)) << 16);
    if (cmask == 0u) return;                     // neither column keeps anything
    const int hmin = __ffs(cmask) - 1;
    const int hmax = 31 - __clz(cmask);

    // --- Phase 2: data loop over kept interval, unconditional loads ---
    const float* xp = x + ((size_t)(bnd * H * W) + w + (size_t)hmin * W) * C + q * 4;
    const int shfl_base = lane & 16;
    float* const outbase = out + ((size_t)b * C + q * 4) * PLANE;

    int curv = -1;
    float4 acc = make_float4(0.f, 0.f, 0.f, 0.f);

    #pragma unroll 4
    for (int h = hmin; h <= hmax; h++) {
        // load with NO control dependency -> hoistable/batchable across unroll
        const float4 val = *reinterpret_cast<const float4*>(xp);
        int vox = __shfl_sync(0xffffffffu, (h < 16) ? v1 : v2, shfl_base | (h & 15));
        if (vox >= 0) {
            if (vox == curv) {
                acc.x += val.x; acc.y += val.y; acc.z += val.z; acc.w += val.w;
            } else {
                if (curv >= 0) {
                    float* dst = outbase + curv;
                    asm volatile("red.global.add.f32 [%0], %1;" :: "l"(dst),             "f"(acc.x) : "memory");
                    asm volatile("red.global.add.f32 [%0], %1;" :: "l"(dst + PLANE),     "f"(acc.y) : "memory");
                    asm volatile("red.global.add.f32 [%0], %1;" :: "l"(dst + 2 * PLANE), "f"(acc.z) : "memory");
                    asm volatile("red.global.add.f32 [%0], %1;" :: "l"(dst + 3 * PLANE), "f"(acc.w) : "memory");
                }
                curv = vox;
                acc = val;
            }
        }
        xp += W * C;
    }
    if (curv >= 0) {
        float* dst = outbase + curv;
        asm volatile("red.global.add.f32 [%0], %1;" :: "l"(dst),             "f"(acc.x) : "memory");
        asm volatile("red.global.add.f32 [%0], %1;" :: "l"(dst + PLANE),     "f"(acc.y) : "memory");
        asm volatile("red.global.add.f32 [%0], %1;" :: "l"(dst + 2 * PLANE), "f"(acc.z) : "memory");
        asm volatile("red.global.add.f32 [%0], %1;" :: "l"(dst + 3 * PLANE), "f"(acc.w) : "memory");
    }
}

// ---------------------------------------------------------------------------
extern "C" void kernel_launch(void* const* d_in, const int* in_sizes, int n_in,
                              void* d_out, int out_size) {
    const float* x    = (const float*)d_in[0];
    const float* intr = (const float*)d_in[1];
    const float* pose = (const float*)d_in[2];
    float* out = (float*)d_out;

    // grid-stride: 1184 blocks x 256 threads covers all OUT_F4 float4
    zero_out<<<1184, 256>>>(out);

    // NCOL*16 = 368,640 threads = 1440 blocks x 256 (exact)
    scatter_kernel<<<1440, 256>>>(x, intr, pose, out);
}